// round 1
// baseline (speedup 1.0000x reference)
#include <cuda_runtime.h>
#include <math.h>

// Problem constants
#define BATCH 8
#define SQ    1024
#define SK    1024
#define DM    512
#define NH    8

// ---------------- device scratch (allocation-free rule: __device__ globals) ----
__device__ float g_Ql[BATCH * SQ * DM];
__device__ float g_Kl[BATCH * SK * DM];
__device__ float g_Vl[BATCH * SK * DM];
__device__ float g_head[BATCH * SQ * DM];
__device__ float g_att[BATCH * SQ * SK];
__device__ float g_Wle[DM * DM];

// ---------------- Wl_eff = sum over heads of Wl blocks -------------------------
__global__ void wl_sum_kernel(const float* __restrict__ Wl, float* __restrict__ Wle) {
    int i = blockIdx.x * blockDim.x + threadIdx.x;
    if (i >= DM * DM) return;
    int k = i / DM;
    int n = i - k * DM;
    float s = 0.f;
#pragma unroll
    for (int h = 0; h < NH; h++) s += Wl[((long)(h * DM + k)) * DM + n];
    Wle[i] = s;
}

// ---------------- 128x128x8 tiled SGEMM, 256 threads, 8x8 per thread ----------
// NT_MODE==0: C = A[M,K] @ B[K,N] (+bias if non-null)
// NT_MODE==1: C = (A[M,K] @ B[N,K]^T) * scale + (-1e9 if mask[n]) , mask per batch
template <int NT_MODE>
__global__ void sgemm_k(const float* __restrict__ A, const float* __restrict__ B,
                        float* __restrict__ C, int M, int N, int K,
                        long sA, long sB, long sC,
                        const float* __restrict__ bias,
                        const int* __restrict__ mask, float scale) {
    const int bz = blockIdx.z;
    A += (long)bz * sA;
    B += (long)bz * sB;
    C += (long)bz * sC;

    const int m0 = blockIdx.y * 128;
    const int n0 = blockIdx.x * 128;

    __shared__ float As[8][128];
    __shared__ float Bs[8][128];

    const int t = threadIdx.x;               // 0..255
    const int arow = t >> 1;                 // 0..127
    const int acol = (t & 1) * 4;            // 0 or 4
    const int trow = t >> 4;                 // 0..15
    const int tcol = t & 15;                 // 0..15

    float acc[8][8];
#pragma unroll
    for (int i = 0; i < 8; i++)
#pragma unroll
        for (int j = 0; j < 8; j++) acc[i][j] = 0.f;

    const float* Ag = A + (long)(m0 + arow) * K + acol;

    for (int k0 = 0; k0 < K; k0 += 8) {
        // load A tile (128x8), transpose into As[k][m]
        float4 a = *(const float4*)(Ag + k0);
        As[acol + 0][arow] = a.x;
        As[acol + 1][arow] = a.y;
        As[acol + 2][arow] = a.z;
        As[acol + 3][arow] = a.w;

        if (NT_MODE) {
            // B is [N,K]; tile rows n0..n0+127, cols k0..k0+7, transpose into Bs[k][n]
            float4 b = *(const float4*)(B + (long)(n0 + arow) * K + k0 + acol);
            Bs[acol + 0][arow] = b.x;
            Bs[acol + 1][arow] = b.y;
            Bs[acol + 2][arow] = b.z;
            Bs[acol + 3][arow] = b.w;
        } else {
            // B is [K,N]; tile 8x128, direct
            int brow = t >> 5;               // 0..7
            int bcol = (t & 31) * 4;         // 0..124
            float4 b = *(const float4*)(B + (long)(k0 + brow) * N + n0 + bcol);
            *(float4*)&Bs[brow][bcol] = b;
        }
        __syncthreads();

#pragma unroll
        for (int kk = 0; kk < 8; kk++) {
            float ra[8], rb[8];
            *(float4*)(ra)     = *(const float4*)&As[kk][trow * 8];
            *(float4*)(ra + 4) = *(const float4*)&As[kk][trow * 8 + 4];
            *(float4*)(rb)     = *(const float4*)&Bs[kk][tcol * 8];
            *(float4*)(rb + 4) = *(const float4*)&Bs[kk][tcol * 8 + 4];
#pragma unroll
            for (int i = 0; i < 8; i++)
#pragma unroll
                for (int j = 0; j < 8; j++) acc[i][j] += ra[i] * rb[j];
        }
        __syncthreads();
    }

    const int crow = m0 + trow * 8;
    const int ccol = n0 + tcol * 8;

    if (NT_MODE) {
        const int* mk = mask + (long)bz * N;
        float pen[8];
#pragma unroll
        for (int j = 0; j < 8; j++) pen[j] = mk[ccol + j] ? -1e9f : 0.f;
#pragma unroll
        for (int i = 0; i < 8; i++) {
            float4 o0, o1;
            o0.x = acc[i][0] * scale + pen[0];
            o0.y = acc[i][1] * scale + pen[1];
            o0.z = acc[i][2] * scale + pen[2];
            o0.w = acc[i][3] * scale + pen[3];
            o1.x = acc[i][4] * scale + pen[4];
            o1.y = acc[i][5] * scale + pen[5];
            o1.z = acc[i][6] * scale + pen[6];
            o1.w = acc[i][7] * scale + pen[7];
            float* cp = C + (long)(crow + i) * N + ccol;
            *(float4*)(cp)     = o0;
            *(float4*)(cp + 4) = o1;
        }
    } else {
        float bv[8];
#pragma unroll
        for (int j = 0; j < 8; j++) bv[j] = bias ? bias[ccol + j] : 0.f;
#pragma unroll
        for (int i = 0; i < 8; i++) {
            float4 o0, o1;
            o0.x = acc[i][0] + bv[0];
            o0.y = acc[i][1] + bv[1];
            o0.z = acc[i][2] + bv[2];
            o0.w = acc[i][3] + bv[3];
            o1.x = acc[i][4] + bv[4];
            o1.y = acc[i][5] + bv[5];
            o1.z = acc[i][6] + bv[6];
            o1.w = acc[i][7] + bv[7];
            float* cp = C + (long)(crow + i) * N + ccol;
            *(float4*)(cp)     = o0;
            *(float4*)(cp + 4) = o1;
        }
    }
}

// ---------------- fused softmax + 8-way head replication ----------------------
// one block per (q, b) row; 256 threads, one float4 per thread (SK=1024)
__global__ void softmax_replicate(float* __restrict__ att, float* __restrict__ out_att) {
    const int q = blockIdx.x;
    const int b = blockIdx.y;
    const int t = threadIdx.x;

    float* row = att + ((long)(b * SQ + q)) * SK;
    float4 v = ((const float4*)row)[t];

    __shared__ float red[256];
    float m = fmaxf(fmaxf(v.x, v.y), fmaxf(v.z, v.w));
    red[t] = m;
    __syncthreads();
#pragma unroll
    for (int s = 128; s > 0; s >>= 1) {
        if (t < s) red[t] = fmaxf(red[t], red[t + s]);
        __syncthreads();
    }
    m = red[0];
    __syncthreads();

    float4 e;
    e.x = expf(v.x - m);
    e.y = expf(v.y - m);
    e.z = expf(v.z - m);
    e.w = expf(v.w - m);
    red[t] = e.x + e.y + e.z + e.w;
    __syncthreads();
#pragma unroll
    for (int s = 128; s > 0; s >>= 1) {
        if (t < s) red[t] += red[t + s];
        __syncthreads();
    }
    float inv = 1.0f / red[0];
    e.x *= inv; e.y *= inv; e.z *= inv; e.w *= inv;

    ((float4*)row)[t] = e;   // head GEMM reads normalized att from scratch

    if (out_att) {
#pragma unroll
        for (int h = 0; h < NH; h++) {
            float4* dst = (float4*)(out_att + (((long)(b * NH + h) * SQ) + q) * SK);
            dst[t] = e;
        }
    }
}

// ---------------- launch --------------------------------------------------------
extern "C" void kernel_launch(void* const* d_in, const int* in_sizes, int n_in,
                              void* d_out, int out_size) {
    const float* Q    = (const float*)d_in[0];
    const float* K    = (const float*)d_in[1];
    const float* V    = (const float*)d_in[2];
    const int*   mask = (const int*)  d_in[3];
    const float* Wq   = (const float*)d_in[4];
    const float* bq   = (const float*)d_in[5];
    const float* Wk   = (const float*)d_in[6];
    const float* bk   = (const float*)d_in[7];
    const float* Wv   = (const float*)d_in[8];
    const float* bv   = (const float*)d_in[9];
    const float* Wl   = (const float*)d_in[10];
    const float* bl   = (const float*)d_in[11];

    float *Ql, *Kl, *Vl, *head, *att, *wle;
    cudaGetSymbolAddress((void**)&Ql,   g_Ql);
    cudaGetSymbolAddress((void**)&Kl,   g_Kl);
    cudaGetSymbolAddress((void**)&Vl,   g_Vl);
    cudaGetSymbolAddress((void**)&head, g_head);
    cudaGetSymbolAddress((void**)&att,  g_att);
    cudaGetSymbolAddress((void**)&wle,  g_Wle);

    float* Yout = (float*)d_out;
    const long YSIZE = (long)BATCH * SQ * DM;
    const long ASIZE = (long)BATCH * NH * SQ * SK;
    float* out_att = ((long)out_size >= YSIZE + ASIZE) ? (Yout + YSIZE) : nullptr;

    const dim3 blk(256);
    const float inv_scale = 1.0f / sqrtf((float)DM);

    // Wl_eff = sum of head blocks of Wl
    wl_sum_kernel<<<(DM * DM + 255) / 256, 256>>>(Wl, wle);

    // projections: [B*SQ, DM] @ [DM, DM] + bias
    sgemm_k<0><<<dim3(DM / 128, (BATCH * SQ) / 128, 1), blk>>>(
        Q, Wq, Ql, BATCH * SQ, DM, DM, 0, 0, 0, bq, nullptr, 1.f);
    sgemm_k<0><<<dim3(DM / 128, (BATCH * SK) / 128, 1), blk>>>(
        K, Wk, Kl, BATCH * SK, DM, DM, 0, 0, 0, bk, nullptr, 1.f);
    sgemm_k<0><<<dim3(DM / 128, (BATCH * SK) / 128, 1), blk>>>(
        V, Wv, Vl, BATCH * SK, DM, DM, 0, 0, 0, bv, nullptr, 1.f);

    // scores: per-batch Ql @ Kl^T * inv_scale + mask * (-1e9)
    sgemm_k<1><<<dim3(SK / 128, SQ / 128, BATCH), blk>>>(
        Ql, Kl, att, SQ, SK, DM,
        (long)SQ * DM, (long)SK * DM, (long)SQ * SK,
        nullptr, mask, inv_scale);

    // softmax + replicate into att_ws output region
    softmax_replicate<<<dim3(SQ, BATCH), 256>>>(att, out_att);

    // head = att @ Vl per batch
    sgemm_k<0><<<dim3(DM / 128, SQ / 128, BATCH), blk>>>(
        att, Vl, head, SQ, DM, SK,
        (long)SQ * SK, (long)SK * DM, (long)SQ * DM,
        nullptr, nullptr, 1.f);

    // Y = head @ Wl_eff + bl
    sgemm_k<0><<<dim3(DM / 128, (BATCH * SQ) / 128, 1), blk>>>(
        head, wle, Yout, BATCH * SQ, DM, DM, 0, 0, 0, bl, nullptr, 1.f);
}

// round 3
// speedup vs baseline: 2.5702x; 2.5702x over previous
#include <cuda_runtime.h>
#include <math.h>
#include <stdint.h>

// Problem constants
#define BATCH 8
#define SQ    1024
#define SK    1024
#define DM    512
#define NH    8

// ---------------- device scratch ----------------------------------------------
__device__ float g_Ql[BATCH * SQ * DM];
__device__ float g_Kl[BATCH * SK * DM];
__device__ float g_VlT[BATCH * DM * SK];     // transposed V projection [b][d][sk]
__device__ float g_head[BATCH * SQ * DM];
__device__ float g_att[BATCH * SQ * SK];
__device__ float g_WleT[DM * DM];
__device__ float g_WqT[DM * DM];
__device__ float g_WkT[DM * DM];
__device__ float g_WvT[DM * DM];

// ---------------- PTX helpers (all sm_80+ features; no 'a'-target needed) ------
__device__ __forceinline__ uint32_t smem_u32(const void* p) {
    uint32_t a;
    asm("{ .reg .u64 t; cvta.to.shared.u64 t, %1; cvt.u32.u64 %0, t; }" : "=r"(a) : "l"(p));
    return a;
}

#define CP_ASYNC16(dst, src) \
    asm volatile("cp.async.cg.shared.global [%0], [%1], 16;" :: "r"(dst), "l"(src) : "memory")
#define CP_COMMIT() asm volatile("cp.async.commit_group;" ::: "memory")
#define CP_WAIT1()  asm volatile("cp.async.wait_group 1;" ::: "memory")
#define CP_WAIT0()  asm volatile("cp.async.wait_group 0;" ::: "memory")

__device__ __forceinline__ uint32_t f2tf32(float v) {
    uint32_t r;
    asm("cvt.rna.tf32.f32 %0, %1;" : "=r"(r) : "f"(v));
    return r;
}

__device__ __forceinline__ void mma_tf32(float* c, const uint32_t* a, const uint32_t* b) {
    asm volatile(
        "mma.sync.aligned.m16n8k8.row.col.f32.tf32.tf32.f32 "
        "{%0,%1,%2,%3}, {%4,%5,%6,%7}, {%8,%9}, {%0,%1,%2,%3};"
        : "+f"(c[0]), "+f"(c[1]), "+f"(c[2]), "+f"(c[3])
        : "r"(a[0]), "r"(a[1]), "r"(a[2]), "r"(a[3]), "r"(b[0]), "r"(b[1]));
}

// ================================================================================
// tf32 mma.sync GEMM: C[M,N] = A[M,K] @ B[N,K]^T
//   A row-major [M,K] (row stride = K), B row-major [N,K] (row stride = K)
// MODE 0: C += bias[n]
// MODE 1: C = C*scale + mask[bz][n]*-1e9
// MODE 2: transposed store: out[b2][n][mloc] + bias[n], b2 = m0/1024, mloc = m0%1024
// grid (N/128, M/128, batches), 256 threads
// ================================================================================
#define BM 128
#define BN 128
#define BK 32
#define LDT 36                                   // padded smem row stride (floats)
#define TILE_F (BM * LDT)                        // floats per tile buffer
#define GEMM_SMEM (4 * TILE_F * 4)               // As0,As1,Bs0,Bs1 = 73728 B

template <int MODE>
__global__ void __launch_bounds__(256, 2) gemm_mma(
    const float* __restrict__ A, const float* __restrict__ B, float* __restrict__ C,
    int Kdim, long sA, long sB, long sC,
    const float* __restrict__ bias, const int* __restrict__ mask, float scale)
{
    extern __shared__ float smem[];
    float* As[2] = { smem,              smem + TILE_F };
    float* Bs[2] = { smem + 2 * TILE_F, smem + 3 * TILE_F };
    const uint32_t smb = smem_u32(smem);

    const int tid = threadIdx.x;
    const int lane = tid & 31, wid = tid >> 5;
    const int wm = wid >> 2, wn = wid & 3;       // 2 x 4 warps
    const int m0 = blockIdx.y * BM, n0 = blockIdx.x * BN, bz = blockIdx.z;

    const float* Ag = A + (long)bz * sA;
    const float* Bg = B + (long)bz * sB;

    // per-thread load slots: 4 float4 per tile
    const int lrow[4] = { (tid + 0)   >> 3, (tid + 256) >> 3,
                          (tid + 512) >> 3, (tid + 768) >> 3 };
    const int lcol = (tid & 7) * 4;

    float acc[4][4][4];
#pragma unroll
    for (int i = 0; i < 4; i++)
#pragma unroll
        for (int j = 0; j < 4; j++)
#pragma unroll
            for (int r = 0; r < 4; r++) acc[i][j][r] = 0.f;

    const int NC = Kdim / BK;

    // ---- issue chunk loads ----
    auto issue = [&](int c, int buf) {
        const long k0 = (long)c * BK;
#pragma unroll
        for (int i = 0; i < 4; i++) {
            uint32_t da = smb + (uint32_t)((buf * TILE_F + lrow[i] * LDT + lcol) * 4);
            CP_ASYNC16(da, Ag + (long)(m0 + lrow[i]) * Kdim + k0 + lcol);
        }
#pragma unroll
        for (int i = 0; i < 4; i++) {
            uint32_t db = smb + (uint32_t)(((2 + buf) * TILE_F + lrow[i] * LDT + lcol) * 4);
            CP_ASYNC16(db, Bg + (long)(n0 + lrow[i]) * Kdim + k0 + lcol);
        }
        CP_COMMIT();
    };

    issue(0, 0);

    for (int c = 0; c < NC; c++) {
        const int buf = c & 1;
        if (c + 1 < NC) { issue(c + 1, buf ^ 1); CP_WAIT1(); }
        else            { CP_WAIT0(); }
        __syncthreads();

        const float* Asb = As[buf];
        const float* Bsb = Bs[buf];
        const int ra = wm * 64 + (lane >> 2);
        const int rb = wn * 32 + (lane >> 2);

#pragma unroll
        for (int kk = 0; kk < 4; kk++) {
            const int kb = kk * 8 + (lane & 3);
            uint32_t af[4][4], bf[4][2];
#pragma unroll
            for (int mt = 0; mt < 4; mt++) {
                const float* p = Asb + (ra + mt * 16) * LDT + kb;
                af[mt][0] = f2tf32(p[0]);
                af[mt][1] = f2tf32(p[8 * LDT]);
                af[mt][2] = f2tf32(p[4]);
                af[mt][3] = f2tf32(p[8 * LDT + 4]);
            }
#pragma unroll
            for (int nt = 0; nt < 4; nt++) {
                const float* p = Bsb + (rb + nt * 8) * LDT + kb;
                bf[nt][0] = f2tf32(p[0]);
                bf[nt][1] = f2tf32(p[4]);
            }
#pragma unroll
            for (int mt = 0; mt < 4; mt++)
#pragma unroll
                for (int nt = 0; nt < 4; nt++)
                    mma_tf32(acc[mt][nt], af[mt], bf[nt]);
        }
        __syncthreads();
    }

    // ---- epilogue ----
    if (MODE == 2) {
        // stage transposed into smem: stage[n_local][m_local], then coalesced store
        float* stage = smem;                     // [128][132]
        __syncthreads();
#pragma unroll
        for (int mt = 0; mt < 4; mt++) {
            const int r0 = wm * 64 + mt * 16 + (lane >> 2);
#pragma unroll
            for (int nt = 0; nt < 4; nt++) {
                const int c0 = wn * 32 + nt * 8 + (lane & 3) * 2;
                stage[(c0    ) * 132 + r0    ] = acc[mt][nt][0];
                stage[(c0 + 1) * 132 + r0    ] = acc[mt][nt][1];
                stage[(c0    ) * 132 + r0 + 8] = acc[mt][nt][2];
                stage[(c0 + 1) * 132 + r0 + 8] = acc[mt][nt][3];
            }
        }
        __syncthreads();
        const int b2 = m0 >> 10, mloc = (m0 & 1023) + (tid & 31) * 4;
        const int rq = tid >> 5;
#pragma unroll
        for (int it = 0; it < 16; it++) {
            const int nr = rq + it * 8;
            float4 v = *(const float4*)&stage[nr * 132 + (tid & 31) * 4];
            const float bb = bias[n0 + nr];
            v.x += bb; v.y += bb; v.z += bb; v.w += bb;
            *(float4*)&C[(long)b2 * ((long)DM * SK) + (long)(n0 + nr) * SK + mloc] = v;
        }
        return;
    }

    float* Cg = C + (long)bz * sC;
#pragma unroll
    for (int mt = 0; mt < 4; mt++) {
        const int r0 = m0 + wm * 64 + mt * 16 + (lane >> 2);
#pragma unroll
        for (int nt = 0; nt < 4; nt++) {
            const int c0 = n0 + wn * 32 + nt * 8 + (lane & 3) * 2;
            float2 v0 = { acc[mt][nt][0], acc[mt][nt][1] };
            float2 v1 = { acc[mt][nt][2], acc[mt][nt][3] };
            if (MODE == 0) {
                if (bias) {
                    v0.x += bias[c0]; v0.y += bias[c0 + 1];
                    v1.x += bias[c0]; v1.y += bias[c0 + 1];
                }
            } else { // MODE 1
                const int* mk = mask + (long)bz * SK;
                float p0 = mk[c0] ? -1e9f : 0.f, p1 = mk[c0 + 1] ? -1e9f : 0.f;
                v0.x = v0.x * scale + p0; v0.y = v0.y * scale + p1;
                v1.x = v1.x * scale + p0; v1.y = v1.y * scale + p1;
            }
            *(float2*)&Cg[(long)r0 * gridDim.x * BN + c0]       = v0;
            *(float2*)&Cg[(long)(r0 + 8) * gridDim.x * BN + c0] = v1;
        }
    }
}

// ================================================================================
// helper kernels
// ================================================================================
__global__ void transpose512(const float* __restrict__ in, float* __restrict__ out) {
    __shared__ float t[32][33];
    int bx = blockIdx.x * 32, by = blockIdx.y * 32;
    for (int i = threadIdx.y; i < 32; i += 8)
        t[i][threadIdx.x] = in[(by + i) * DM + bx + threadIdx.x];
    __syncthreads();
    for (int i = threadIdx.y; i < 32; i += 8)
        out[(bx + i) * DM + by + threadIdx.x] = t[threadIdx.x][i];
}

__global__ void wl_sumT_kernel(const float* __restrict__ Wl, float* __restrict__ WleT) {
    int i = blockIdx.x * blockDim.x + threadIdx.x;
    if (i >= DM * DM) return;
    int k = i >> 9, n = i & 511;
    float s = 0.f;
#pragma unroll
    for (int h = 0; h < NH; h++) s += Wl[((long)(h * DM + k)) * DM + n];
    WleT[n * DM + k] = s;
}

// fused softmax + 8-way head replication; one block per (q, b)
__global__ void softmax_replicate(float* __restrict__ att, float* __restrict__ out_att) {
    const int q = blockIdx.x, b = blockIdx.y, t = threadIdx.x;
    float* row = att + ((long)(b * SQ + q)) * SK;
    float4 v = ((const float4*)row)[t];

    __shared__ float red[256];
    float m = fmaxf(fmaxf(v.x, v.y), fmaxf(v.z, v.w));
    red[t] = m;
    __syncthreads();
#pragma unroll
    for (int s = 128; s > 0; s >>= 1) {
        if (t < s) red[t] = fmaxf(red[t], red[t + s]);
        __syncthreads();
    }
    m = red[0];
    __syncthreads();

    float4 e;
    e.x = expf(v.x - m); e.y = expf(v.y - m);
    e.z = expf(v.z - m); e.w = expf(v.w - m);
    red[t] = e.x + e.y + e.z + e.w;
    __syncthreads();
#pragma unroll
    for (int s = 128; s > 0; s >>= 1) {
        if (t < s) red[t] += red[t + s];
        __syncthreads();
    }
    float inv = 1.0f / red[0];
    e.x *= inv; e.y *= inv; e.z *= inv; e.w *= inv;

    ((float4*)row)[t] = e;
    if (out_att) {
#pragma unroll
        for (int h = 0; h < NH; h++)
            ((float4*)(out_att + (((long)(b * NH + h) * SQ) + q) * SK))[t] = e;
    }
}

// ================================================================================
// launch
// ================================================================================
extern "C" void kernel_launch(void* const* d_in, const int* in_sizes, int n_in,
                              void* d_out, int out_size) {
    const float* Q    = (const float*)d_in[0];
    const float* K    = (const float*)d_in[1];
    const float* V    = (const float*)d_in[2];
    const int*   mask = (const int*)  d_in[3];
    const float* Wq   = (const float*)d_in[4];
    const float* bq   = (const float*)d_in[5];
    const float* Wk   = (const float*)d_in[6];
    const float* bk   = (const float*)d_in[7];
    const float* Wv   = (const float*)d_in[8];
    const float* bv   = (const float*)d_in[9];
    const float* Wl   = (const float*)d_in[10];
    const float* bl   = (const float*)d_in[11];

    float *Ql, *Kl, *VlT, *head, *att, *wleT, *wqT, *wkT, *wvT;
    cudaGetSymbolAddress((void**)&Ql,   g_Ql);
    cudaGetSymbolAddress((void**)&Kl,   g_Kl);
    cudaGetSymbolAddress((void**)&VlT,  g_VlT);
    cudaGetSymbolAddress((void**)&head, g_head);
    cudaGetSymbolAddress((void**)&att,  g_att);
    cudaGetSymbolAddress((void**)&wleT, g_WleT);
    cudaGetSymbolAddress((void**)&wqT,  g_WqT);
    cudaGetSymbolAddress((void**)&wkT,  g_WkT);
    cudaGetSymbolAddress((void**)&wvT,  g_WvT);

    float* Yout = (float*)d_out;
    const long YSIZE = (long)BATCH * SQ * DM;
    const long ASIZE = (long)BATCH * NH * SQ * SK;
    float* out_att = ((long)out_size >= YSIZE + ASIZE) ? (Yout + YSIZE) : nullptr;
    const float inv_scale = 1.0f / sqrtf((float)DM);

    cudaFuncSetAttribute(gemm_mma<0>, cudaFuncAttributeMaxDynamicSharedMemorySize, GEMM_SMEM);
    cudaFuncSetAttribute(gemm_mma<1>, cudaFuncAttributeMaxDynamicSharedMemorySize, GEMM_SMEM);
    cudaFuncSetAttribute(gemm_mma<2>, cudaFuncAttributeMaxDynamicSharedMemorySize, GEMM_SMEM);

    // weight transposes / head-summed output weight
    transpose512<<<dim3(16, 16), dim3(32, 8)>>>(Wq, wqT);
    transpose512<<<dim3(16, 16), dim3(32, 8)>>>(Wk, wkT);
    transpose512<<<dim3(16, 16), dim3(32, 8)>>>(Wv, wvT);
    wl_sumT_kernel<<<(DM * DM + 255) / 256, 256>>>(Wl, wleT);

    // projections: [B*S, 512] @ W^T
    gemm_mma<0><<<dim3(DM / BN, (BATCH * SQ) / BM, 1), 256, GEMM_SMEM>>>(
        Q, wqT, Ql, DM, 0, 0, 0, bq, nullptr, 0.f);
    gemm_mma<0><<<dim3(DM / BN, (BATCH * SK) / BM, 1), 256, GEMM_SMEM>>>(
        K, wkT, Kl, DM, 0, 0, 0, bk, nullptr, 0.f);
    gemm_mma<2><<<dim3(DM / BN, (BATCH * SK) / BM, 1), 256, GEMM_SMEM>>>(
        V, wvT, VlT, DM, 0, 0, 0, bv, nullptr, 0.f);

    // scores = Ql @ Kl^T * s + mask
    gemm_mma<1><<<dim3(SK / BN, SQ / BM, BATCH), 256, GEMM_SMEM>>>(
        Ql, Kl, att, DM, (long)SQ * DM, (long)SK * DM, (long)SQ * SK,
        nullptr, mask, inv_scale);

    // softmax + replicate into att_ws output region
    softmax_replicate<<<dim3(SQ, BATCH), 256>>>(att, out_att);

    // head = att @ Vl  (B = VlT [DM][SK], K-major)
    gemm_mma<0><<<dim3(DM / BN, SQ / BM, BATCH), 256, GEMM_SMEM>>>(
        att, VlT, head, SK, (long)SQ * SK, (long)DM * SK, (long)SQ * DM,
        nullptr, nullptr, 0.f);

    // Y = head @ Wl_eff + bl
    gemm_mma<0><<<dim3(DM / BN, (BATCH * SQ) / BM, 1), 256, GEMM_SMEM>>>(
        head, wleT, Yout, DM, 0, 0, 0, bl, nullptr, 0.f);
}